// round 12
// baseline (speedup 1.0000x reference)
#include <cuda_runtime.h>
#include <cuda_bf16.h>
#include <cstdint>
#include <cstddef>

// SRNN_multi: 2-layer spiking RNN, N=512, T=1000, H=128, DOUT=20.
//   prep:  permute weight matrices once into gmem
//   k1:    pre1 = x @ Wi1^T + bi1 + bh1   (persistent double-buffered GEMM)
//   k2a:   s1(t) recurrence -> mask stream (2 rows/warp interleaved)
//   k2b1:  gi(row,t) = b2 + s1(t)@Wi2^T   (4096-warp parallel, no smem)
//   k2b2:  s2(t) recurrence + counts      (2 rows/warp interleaved)
//   out = bo + (sum_t s2) @ Wo^T / T

#define NB   512
#define TS   1000
#define HD   128
#define DOUT 20
#define MTOT (NB * TS)
#define XS   66
#define NTILES (MTOT / 64)      // 8000
#define K1_GRID 148

typedef unsigned long long ull;

// pre1 scratch, permuted: [(row*TS+t)*128 + lane*4 + q] = val[lane + 32*q].
// Reused by k2b1 as gi storage. +2048 floats pad for deep prefetch overshoot.
__device__ float g_pre1[(size_t)MTOT * HD + 2048];
// s1 spike masks per (row,t): two 64-bit words (k 0-63, 64-127)
__device__ ulonglong2 g_s1[(size_t)NB * TS + 16];
// permuted weights: P[k*128 + (j&31)*4 + (j>>5)] = W[j*128 + k]
__device__ float g_Wi1p[HD * HD], g_Wh1p[HD * HD], g_Wi2p[HD * HD], g_Wh2p[HD * HD];

__device__ __forceinline__ ull pk2(float lo, float hi) {
    ull r; asm("mov.b64 %0, {%1, %2};" : "=l"(r) : "f"(lo), "f"(hi)); return r;
}
__device__ __forceinline__ float2 upk2(ull v) {
    float2 r; asm("mov.b64 {%0, %1}, %2;" : "=f"(r.x), "=f"(r.y) : "l"(v)); return r;
}
__device__ __forceinline__ void fma2(ull& d, ull a, ull b) {
    asm("fma.rn.f32x2 %0, %1, %2, %0;" : "+l"(d) : "l"(a), "l"(b));
}
__device__ __forceinline__ void add2(ull& d, ull a) {
    asm("add.rn.f32x2 %0, %1, %0;" : "+l"(d) : "l"(a));
}

// ---------------------------------------------------------------------------
// prep: one-time weight permutation.
// ---------------------------------------------------------------------------
__global__ void prep(const float* __restrict__ Wi1, const float* __restrict__ Wh1,
                     const float* __restrict__ Wi2, const float* __restrict__ Wh2)
{
    int i = blockIdx.x * blockDim.x + threadIdx.x;
    if (i < HD * HD) {
        int j = i >> 7, k = i & 127;
        int d = k * 128 + ((j & 31) << 2) + (j >> 5);
        g_Wi1p[d] = Wi1[i];
        g_Wh1p[d] = Wh1[i];
        g_Wi2p[d] = Wi2[i];
        g_Wh2p[d] = Wh2[i];
    }
}

// ---------------------------------------------------------------------------
// Kernel 1: pre1 = x @ Wi1^T + (bi1+bh1).
// PERSISTENT: 148 CTAs x 256 thr, 1/SM. Weights staged in smem ONCE; x tiles
// (64 rows) double-buffered, next tile LDG-prefetched to registers before the
// compute block so global latency is hidden. Inner math identical to R7.
// ---------------------------------------------------------------------------
__global__ void __launch_bounds__(256, 1) k1_gemm(
    const float* __restrict__ x, const float* __restrict__ bi1,
    const float* __restrict__ bh1)
{
    extern __shared__ float sm[];
    float* ws = sm;                       // 16384 f: permuted Wi1
    float* xb[2] = { sm + 16384, sm + 16384 + 128 * XS };

    const int tid = threadIdx.x, lane = tid & 31, warp = tid >> 5;

    // stage permuted Wi1 once
    {
        const float4* Wp = (const float4*)g_Wi1p;
        float4* w4 = (float4*)ws;
        for (int i = tid; i < 4096; i += 256) w4[i] = Wp[i];
    }
    // stage first tile
    {
        const float4* xg = (const float4*)x + (size_t)blockIdx.x * 2048;
        float* xT = xb[0];
        for (int i = tid; i < 2048; i += 256) {
            float4 v = xg[i];
            int r = i >> 5, c = (i & 31) << 2;
            xT[(c + 0) * XS + r] = v.x;
            xT[(c + 1) * XS + r] = v.y;
            xT[(c + 2) * XS + r] = v.z;
            xT[(c + 3) * XS + r] = v.w;
        }
    }
    __syncthreads();

    const ull b01 = pk2(bi1[lane]      + bh1[lane],      bi1[lane + 32] + bh1[lane + 32]);
    const ull b23 = pk2(bi1[lane + 64] + bh1[lane + 64], bi1[lane + 96] + bh1[lane + 96]);
    const float4* W4 = (const float4*)ws;

    int cur = 0;
    for (int tile = blockIdx.x; tile < NTILES; tile += gridDim.x) {
        const int nt = tile + gridDim.x;
        const bool has = nt < NTILES;

        // prefetch next tile into registers (latency overlaps compute below)
        float4 pf[8];
        {
            const float4* xg = (const float4*)x + (size_t)(has ? nt : tile) * 2048;
#pragma unroll
            for (int j = 0; j < 8; ++j) pf[j] = xg[tid + 256 * j];
        }

        // ---- compute on xb[cur] ----
        ull a01[4], a23[4];
        ull acc1[4], acc3[4];     // q=1,3 accumulators
#pragma unroll
        for (int p = 0; p < 4; ++p) { a01[p] = b01; a23[p] = b23; }
        // NOTE: layout matches R7: acc[q][p]; here a01 = q0, acc1 = q1, etc.
        ull* accq[4];
        // (use explicit arrays to keep register allocation flat)
        ull A0[4], A1[4], A2[4], A3[4];
#pragma unroll
        for (int p = 0; p < 4; ++p) {
            A0[p] = pk2(bi1[lane]      + bh1[lane],      bi1[lane]      + bh1[lane]);
        }
        // -- revert to the proven R7 structure: acc[4][4] --
        ull acc[4][4];
#pragma unroll
        for (int q = 0; q < 4; ++q) {
            const float2 bq = (q < 2) ? upk2(b01) : upk2(b23);
            const float b = (q & 1) ? bq.y : bq.x;
            const ull bd = pk2(b, b);
#pragma unroll
            for (int p = 0; p < 4; ++p) acc[q][p] = bd;
        }

        const float* xw = xb[cur] + warp * 8;
#pragma unroll 4
        for (int k = 0; k < 128; ++k) {
            const float4 wv = W4[k * 32 + lane];
            const ull wd0 = pk2(wv.x, wv.x), wd1 = pk2(wv.y, wv.y);
            const ull wd2 = pk2(wv.z, wv.z), wd3 = pk2(wv.w, wv.w);
            const ull* xp = (const ull*)(xw + k * XS);
#pragma unroll
            for (int p = 0; p < 4; ++p) {
                const ull xv = xp[p];
                fma2(acc[0][p], xv, wd0);
                fma2(acc[1][p], xv, wd1);
                fma2(acc[2][p], xv, wd2);
                fma2(acc[3][p], xv, wd3);
            }
        }

        const size_t rbase = (size_t)tile * 64 + warp * 8;
#pragma unroll
        for (int p = 0; p < 4; ++p) {
            const float2 a0 = upk2(acc[0][p]), a1 = upk2(acc[1][p]);
            const float2 a2 = upk2(acc[2][p]), a3 = upk2(acc[3][p]);
            float4 e; e.x = a0.x; e.y = a1.x; e.z = a2.x; e.w = a3.x;
            float4 o; o.x = a0.y; o.y = a1.y; o.z = a2.y; o.w = a3.y;
            *(float4*)(g_pre1 + (rbase + 2 * p)     * 128 + lane * 4) = e;
            *(float4*)(g_pre1 + (rbase + 2 * p + 1) * 128 + lane * 4) = o;
        }

        // ---- store prefetched tile into the other buffer ----
        if (has) {
            float* xT = xb[cur ^ 1];
#pragma unroll
            for (int j = 0; j < 8; ++j) {
                const int i = tid + 256 * j;
                const int r = i >> 5, c = (i & 31) << 2;
                xT[(c + 0) * XS + r] = pf[j].x;
                xT[(c + 1) * XS + r] = pf[j].y;
                xT[(c + 2) * XS + r] = pf[j].z;
                xT[(c + 3) * XS + r] = pf[j].w;
            }
        }
        __syncthreads();
        cur ^= 1;
        (void)accq; (void)A0; (void)A1; (void)A2; (void)A3; (void)a01; (void)a23;
        (void)acc1; (void)acc3;
    }
}

// ---------------------------------------------------------------------------
// Branchless next-set-bit over a 128-bit mask (ascending k).
// ---------------------------------------------------------------------------
__device__ __forceinline__ int nextbit(ull& m0, ull& m1) {
    const bool lo = (m0 != 0ull);
    const ull  w  = lo ? m0 : m1;
    const ull  wc = w & (w - 1);
    const int  k  = (lo ? 0 : 64) + __ffsll((long long)w) - 1;
    m0 = lo ? wc : m0;
    m1 = lo ? m1 : wc;
    return k;
}

// Fixed-trip-count, depth-2 software-pipelined sparse accumulate.
// Ascending-k order (identical to all previous passing rounds).
__device__ __forceinline__ void walkp(
    const ulonglong2* __restrict__ W, ull m0, ull m1, int lane, ull& a, ull& b)
{
    int n = __popcll(m0) + __popcll(m1);
    if (n == 0) return;
    ulonglong2 va = W[nextbit(m0, m1) * 32 + lane];
    if (n >= 2) {
        ulonglong2 vb = W[nextbit(m0, m1) * 32 + lane];
        for (int i = 2; i < n; ++i) {
            ulonglong2 vc = W[nextbit(m0, m1) * 32 + lane];
            add2(a, va.x); add2(b, va.y);
            va = vb; vb = vc;
        }
        add2(a, va.x); add2(b, va.y);
        va = vb;
    }
    add2(a, va.x); add2(b, va.y);
}

// predicated lane-0 store (no BSSY/BSYNC)
__device__ __forceinline__ void stg_mask(ulonglong2* p, ull lo, ull hi, int lane) {
    asm volatile(
        "{\n\t.reg .pred p0;\n\tsetp.eq.s32 p0, %0, 0;\n\t"
        "@p0 st.global.v2.u64 [%1], {%2, %3};\n\t}"
        :: "r"(lane), "l"(p), "l"(lo), "l"(hi) : "memory");
}

// ---------------------------------------------------------------------------
// Kernel 2a: layer-1 recurrence, TWO rows per warp (interleaved chains).
// 64 CTAs x 128 thr; warp handles rows 2w, 2w+1 of its CTA's 8-row group.
// ---------------------------------------------------------------------------
__global__ void __launch_bounds__(128) k2a(void)
{
    extern __shared__ float sm[];      // 16384 f = permuted Wh1
    const int tid = threadIdx.x, lane = tid & 31, warp = tid >> 5;

    {
        const float4* Wp = (const float4*)g_Wh1p;
        float4* w4 = (float4*)sm;
        for (int i = tid; i < 4096; i += 128) w4[i] = Wp[i];
    }
    __syncthreads();

    const ulonglong2* W1 = (const ulonglong2*)sm;
    const int rA = (blockIdx.x * 4 + warp) * 2;
    const int rB = rA + 1;
    const float4* preA = (const float4*)g_pre1 + (size_t)rA * TS * 32 + lane;
    const float4* preB = (const float4*)g_pre1 + (size_t)rB * TS * 32 + lane;
    ulonglong2* msA = g_s1 + (size_t)rA * TS;
    ulonglong2* msB = g_s1 + (size_t)rB * TS;

    ull sA_lo = 0, sA_hi = 0, sB_lo = 0, sB_hi = 0;

    float4 fA0 = preA[0 * 32], fA1 = preA[1 * 32], fA2 = preA[2 * 32], fA3 = preA[3 * 32];
    float4 fB0 = preB[0 * 32], fB1 = preB[1 * 32], fB2 = preB[2 * 32], fB3 = preB[3 * 32];

    auto stepRow = [&](const float4& cur, ull& s_lo, ull& s_hi, ulonglong2* ms, int t) {
        ull h01 = pk2(cur.x, cur.y), h23 = pk2(cur.z, cur.w);
        walkp(W1, s_lo, s_hi, lane, h01, h23);
        const float2 ha = upk2(h01), hb = upk2(h23);
        const unsigned q0 = __ballot_sync(0xffffffffu, ha.x >= 1.0f);
        const unsigned q1 = __ballot_sync(0xffffffffu, ha.y >= 1.0f);
        const unsigned q2 = __ballot_sync(0xffffffffu, hb.x >= 1.0f);
        const unsigned q3 = __ballot_sync(0xffffffffu, hb.y >= 1.0f);
        s_lo = (ull)q0 | ((ull)q1 << 32);
        s_hi = (ull)q2 | ((ull)q3 << 32);
        stg_mask(ms + t, s_lo, s_hi, lane);
    };

    for (int t = 0; t < TS; t += 4) {
        stepRow(fA0, sA_lo, sA_hi, msA, t + 0); fA0 = preA[(t + 4) * 32];
        stepRow(fB0, sB_lo, sB_hi, msB, t + 0); fB0 = preB[(t + 4) * 32];
        stepRow(fA1, sA_lo, sA_hi, msA, t + 1); fA1 = preA[(t + 5) * 32];
        stepRow(fB1, sB_lo, sB_hi, msB, t + 1); fB1 = preB[(t + 5) * 32];
        stepRow(fA2, sA_lo, sA_hi, msA, t + 2); fA2 = preA[(t + 6) * 32];
        stepRow(fB2, sB_lo, sB_hi, msB, t + 2); fB2 = preB[(t + 6) * 32];
        stepRow(fA3, sA_lo, sA_hi, msA, t + 3); fA3 = preA[(t + 7) * 32];
        stepRow(fB3, sB_lo, sB_hi, msB, t + 3); fB3 = preB[(t + 7) * 32];
    }
}

// ---------------------------------------------------------------------------
// Kernel 2b1: gi(row,t) = b2 + s1(t)@Wi2^T. 512 CTAs x 256 thr = 4096 warps;
// warp w: row = w>>3, t-strip = (w&7)*125. Weights via L1-resident gmem
// (no smem -> no occupancy cap, no staging sync).
// ---------------------------------------------------------------------------
__global__ void __launch_bounds__(256) k2b1(
    const float* __restrict__ bi2, const float* __restrict__ bh2)
{
    const int tid = threadIdx.x, lane = tid & 31;
    const int w    = blockIdx.x * 8 + (tid >> 5);
    const int row  = w >> 3;
    const int t0   = (w & 7) * (TS / 8);
    const int t1   = t0 + (TS / 8);

    const ulonglong2* W2i = (const ulonglong2*)(const void*)g_Wi2p;

    const ull b01 = pk2(bi2[lane]      + bh2[lane],      bi2[lane + 32] + bh2[lane + 32]);
    const ull b23 = pk2(bi2[lane + 64] + bh2[lane + 64], bi2[lane + 96] + bh2[lane + 96]);

    const ulonglong2* ms = g_s1 + (size_t)row * TS;
    ulonglong2* gi = (ulonglong2*)(void*)g_pre1 + (size_t)row * TS * 32 + lane;

    ulonglong2 mA = ms[t0], mB = ms[t0 + 1];
    for (int t = t0; t < t1; ++t) {
        const ulonglong2 m = mA;
        mA = mB;
        mB = ms[min(t + 2, t1 - 1)];
        ull g01 = b01, g23 = b23;
        walkp(W2i, m.x, m.y, lane, g01, g23);
        ulonglong2 o; o.x = g01; o.y = g23;
        gi[(size_t)t * 32] = o;
    }
}

// ---------------------------------------------------------------------------
// Kernel 2b2: layer-2 recurrence + counts + output, TWO rows per warp.
// 64 CTAs x 128 thr.
// ---------------------------------------------------------------------------
__global__ void __launch_bounds__(128) k2b2(
    const float* __restrict__ Wo, const float* __restrict__ bo,
    float* __restrict__ out)
{
    extern __shared__ float sm[];      // 16384 f = permuted Wh2
    const int tid = threadIdx.x, lane = tid & 31, warp = tid >> 5;

    {
        const float4* Wp = (const float4*)g_Wh2p;
        float4* w4 = (float4*)sm;
        for (int i = tid; i < 4096; i += 128) w4[i] = Wp[i];
    }
    __syncthreads();

    const ulonglong2* W2h = (const ulonglong2*)sm;
    const int rA = (blockIdx.x * 4 + warp) * 2;
    const int rB = rA + 1;
    const float4* giA = (const float4*)g_pre1 + (size_t)rA * TS * 32 + lane;
    const float4* giB = (const float4*)g_pre1 + (size_t)rB * TS * 32 + lane;

    ull rA_lo = 0, rA_hi = 0, rB_lo = 0, rB_hi = 0;
    int cA[4] = {0, 0, 0, 0}, cB[4] = {0, 0, 0, 0};

    float4 fA0 = giA[0 * 32], fA1 = giA[1 * 32], fA2 = giA[2 * 32], fA3 = giA[3 * 32];
    float4 fB0 = giB[0 * 32], fB1 = giB[1 * 32], fB2 = giB[2 * 32], fB3 = giB[3 * 32];

    auto stepRow = [&](const float4& cur, ull& r_lo, ull& r_hi, int* c) {
        ull g01 = pk2(cur.x, cur.y), g23 = pk2(cur.z, cur.w);
        walkp(W2h, r_lo, r_hi, lane, g01, g23);
        const float2 ga = upk2(g01), gb = upk2(g23);
        const bool p0 = (ga.x >= 1.0f), p1 = (ga.y >= 1.0f);
        const bool p2 = (gb.x >= 1.0f), p3 = (gb.y >= 1.0f);
        const unsigned q0 = __ballot_sync(0xffffffffu, p0);
        const unsigned q1 = __ballot_sync(0xffffffffu, p1);
        const unsigned q2 = __ballot_sync(0xffffffffu, p2);
        const unsigned q3 = __ballot_sync(0xffffffffu, p3);
        r_lo = (ull)q0 | ((ull)q1 << 32);
        r_hi = (ull)q2 | ((ull)q3 << 32);
        c[0] += p0; c[1] += p1; c[2] += p2; c[3] += p3;
    };

    for (int t = 0; t < TS; t += 4) {
        stepRow(fA0, rA_lo, rA_hi, cA); fA0 = giA[(t + 4) * 32];
        stepRow(fB0, rB_lo, rB_hi, cB); fB0 = giB[(t + 4) * 32];
        stepRow(fA1, rA_lo, rA_hi, cA); fA1 = giA[(t + 5) * 32];
        stepRow(fB1, rB_lo, rB_hi, cB); fB1 = giB[(t + 5) * 32];
        stepRow(fA2, rA_lo, rA_hi, cA); fA2 = giA[(t + 6) * 32];
        stepRow(fB2, rB_lo, rB_hi, cB); fB2 = giB[(t + 6) * 32];
        stepRow(fA3, rA_lo, rA_hi, cA); fA3 = giA[(t + 7) * 32];
        stepRow(fB3, rB_lo, rB_hi, cB); fB3 = giB[(t + 7) * 32];
    }

    auto epi = [&](const int* c, int row) {
        const float f0 = (float)c[0], f1 = (float)c[1], f2 = (float)c[2], f3 = (float)c[3];
#pragma unroll
        for (int o = 0; o < DOUT; ++o) {
            const float* wr = Wo + o * HD;
            float p = f0 * wr[lane] + f1 * wr[lane + 32]
                    + f2 * wr[lane + 64] + f3 * wr[lane + 96];
#pragma unroll
            for (int s = 16; s; s >>= 1) p += __shfl_xor_sync(0xffffffffu, p, s);
            if (lane == 0) out[row * DOUT + o] = bo[o] + p * (1.0f / (float)TS);
        }
    };
    epi(cA, rA);
    epi(cB, rB);
}

extern "C" void kernel_launch(void* const* d_in, const int* in_sizes, int n_in,
                              void* d_out, int out_size)
{
    const float* x   = (const float*)d_in[0];
    const float* Wi1 = (const float*)d_in[1];
    const float* bi1 = (const float*)d_in[2];
    const float* Wh1 = (const float*)d_in[3];
    const float* bh1 = (const float*)d_in[4];
    const float* Wi2 = (const float*)d_in[5];
    const float* bi2 = (const float*)d_in[6];
    const float* Wh2 = (const float*)d_in[7];
    const float* bh2 = (const float*)d_in[8];
    const float* Wo  = (const float*)d_in[9];
    const float* bo  = (const float*)d_in[10];
    float* out = (float*)d_out;

    const int k1_smem = (16384 + 2 * 128 * XS) * 4;   // 133120 B (1 CTA/SM)
    const int w_smem  = 16384 * 4;                     // 65536 B
    cudaFuncSetAttribute(k1_gemm, cudaFuncAttributeMaxDynamicSharedMemorySize, k1_smem);
    cudaFuncSetAttribute(k2a,  cudaFuncAttributeMaxDynamicSharedMemorySize, w_smem);
    cudaFuncSetAttribute(k2b2, cudaFuncAttributeMaxDynamicSharedMemorySize, w_smem);

    prep<<<64, 256>>>(Wi1, Wh1, Wi2, Wh2);
    k1_gemm<<<K1_GRID, 256, k1_smem>>>(x, bi1, bh1);
    k2a<<<NB / 8, 128, w_smem>>>();
    k2b1<<<512, 256>>>(bi2, bh2);
    k2b2<<<NB / 8, 128, w_smem>>>(Wo, bo, out);
}

// round 13
// speedup vs baseline: 1.0497x; 1.0497x over previous
#include <cuda_runtime.h>
#include <cuda_bf16.h>
#include <cstdint>
#include <cstddef>

// SRNN_multi: 2-layer spiking RNN, N=512, T=1000, H=128, DOUT=20.
//   prep:  permute weight matrices once into gmem
//   k1:    pre1 = x @ Wi1^T + bi1 + bh1   (R10 inner loop, 4 tiles/CTA)
//   k2a:   s1(t) recurrence -> mask stream (2 rows/warp interleaved)
//   k2b1:  gi(row,t) = b2 + s1(t)@Wi2^T   (4096-warp parallel, no smem)
//   k2b2:  s2(t) recurrence + counts      (2 rows/warp interleaved)
//   out = bo + (sum_t s2) @ Wo^T / T

#define NB   512
#define TS   1000
#define HD   128
#define DOUT 20
#define MTOT (NB * TS)
#define XS   66
#define NTILES (MTOT / 64)        // 8000
#define TILES_PER_CTA 4

typedef unsigned long long ull;

// pre1 scratch, permuted: [(row*TS+t)*128 + lane*4 + q] = val[lane + 32*q].
// Reused by k2b1 as gi storage. +2048 floats pad for deep prefetch overshoot.
__device__ float g_pre1[(size_t)MTOT * HD + 2048];
// s1 spike masks per (row,t): two 64-bit words (k 0-63, 64-127)
__device__ ulonglong2 g_s1[(size_t)NB * TS + 16];
// permuted weights: P[k*128 + (j&31)*4 + (j>>5)] = W[j*128 + k]
__device__ float g_Wi1p[HD * HD], g_Wh1p[HD * HD], g_Wi2p[HD * HD], g_Wh2p[HD * HD];

__device__ __forceinline__ ull pk2(float lo, float hi) {
    ull r; asm("mov.b64 %0, {%1, %2};" : "=l"(r) : "f"(lo), "f"(hi)); return r;
}
__device__ __forceinline__ float2 upk2(ull v) {
    float2 r; asm("mov.b64 {%0, %1}, %2;" : "=f"(r.x), "=f"(r.y) : "l"(v)); return r;
}
__device__ __forceinline__ void fma2(ull& d, ull a, ull b) {
    asm("fma.rn.f32x2 %0, %1, %2, %0;" : "+l"(d) : "l"(a), "l"(b));
}
__device__ __forceinline__ void add2(ull& d, ull a) {
    asm("add.rn.f32x2 %0, %1, %0;" : "+l"(d) : "l"(a));
}

// ---------------------------------------------------------------------------
// prep: one-time weight permutation.
// ---------------------------------------------------------------------------
__global__ void prep(const float* __restrict__ Wi1, const float* __restrict__ Wh1,
                     const float* __restrict__ Wi2, const float* __restrict__ Wh2)
{
    int i = blockIdx.x * blockDim.x + threadIdx.x;
    if (i < HD * HD) {
        int j = i >> 7, k = i & 127;
        int d = k * 128 + ((j & 31) << 2) + (j >> 5);
        g_Wi1p[d] = Wi1[i];
        g_Wh1p[d] = Wh1[i];
        g_Wi2p[d] = Wi2[i];
        g_Wh2p[d] = Wh2[i];
    }
}

// ---------------------------------------------------------------------------
// Kernel 1: pre1 = x @ Wi1^T + (bi1+bh1).
// R10's proven inner loop (warp = 8 rows x 128 cols, row-pair f32x2 accs),
// wrapped in a 4-tile outer loop so the 64KB weight stage amortizes 4x.
// 2000 CTAs x 256 thr, 2 CTAs/SM.
// ---------------------------------------------------------------------------
__global__ void __launch_bounds__(256, 2) k1_gemm(
    const float* __restrict__ x, const float* __restrict__ bi1,
    const float* __restrict__ bh1)
{
    extern __shared__ float sm[];
    float* ws = sm;            // 16384 f: permuted Wi1
    float* xT = sm + 16384;    // 128*XS f: xT[k*XS + r]

    const int tid = threadIdx.x, lane = tid & 31, warp = tid >> 5;

    // stage permuted Wi1 once per CTA (conflict-free float4 copy)
    {
        const float4* Wp = (const float4*)g_Wi1p;
        float4* w4 = (float4*)ws;
        for (int i = tid; i < 4096; i += 256) w4[i] = Wp[i];
    }

    auto stage_x = [&](int tile) {
        const float4* xg = (const float4*)x + (size_t)tile * 2048;
        for (int i = tid; i < 2048; i += 256) {
            float4 v = xg[i];
            int r = i >> 5, c = (i & 31) << 2;
            xT[(c + 0) * XS + r] = v.x;
            xT[(c + 1) * XS + r] = v.y;
            xT[(c + 2) * XS + r] = v.z;
            xT[(c + 3) * XS + r] = v.w;
        }
    };

    const int tile0 = blockIdx.x * TILES_PER_CTA;
    stage_x(tile0);
    __syncthreads();

    const ull b01 = pk2(bi1[lane]      + bh1[lane],      bi1[lane + 32] + bh1[lane + 32]);
    const ull b23 = pk2(bi1[lane + 64] + bh1[lane + 64], bi1[lane + 96] + bh1[lane + 96]);
    const float4* W4 = (const float4*)ws;
    const float* xw = xT + warp * 8;

    for (int it = 0; it < TILES_PER_CTA; ++it) {
        const int tile = tile0 + it;

        ull acc[4][4];
        {
            const float2 bA = upk2(b01), bB = upk2(b23);
            const ull bd0 = pk2(bA.x, bA.x), bd1 = pk2(bA.y, bA.y);
            const ull bd2 = pk2(bB.x, bB.x), bd3 = pk2(bB.y, bB.y);
#pragma unroll
            for (int p = 0; p < 4; ++p) {
                acc[0][p] = bd0; acc[1][p] = bd1; acc[2][p] = bd2; acc[3][p] = bd3;
            }
        }

#pragma unroll 4
        for (int k = 0; k < 128; ++k) {
            const float4 wv = W4[k * 32 + lane];
            const ull wd0 = pk2(wv.x, wv.x), wd1 = pk2(wv.y, wv.y);
            const ull wd2 = pk2(wv.z, wv.z), wd3 = pk2(wv.w, wv.w);
            const ull* xp = (const ull*)(xw + k * XS);
#pragma unroll
            for (int p = 0; p < 4; ++p) {
                const ull xv = xp[p];
                fma2(acc[0][p], xv, wd0);
                fma2(acc[1][p], xv, wd1);
                fma2(acc[2][p], xv, wd2);
                fma2(acc[3][p], xv, wd3);
            }
        }

        const size_t rbase = (size_t)tile * 64 + warp * 8;
#pragma unroll
        for (int p = 0; p < 4; ++p) {
            const float2 a0 = upk2(acc[0][p]), a1 = upk2(acc[1][p]);
            const float2 a2 = upk2(acc[2][p]), a3 = upk2(acc[3][p]);
            float4 e; e.x = a0.x; e.y = a1.x; e.z = a2.x; e.w = a3.x;
            float4 o; o.x = a0.y; o.y = a1.y; o.z = a2.y; o.w = a3.y;
            *(float4*)(g_pre1 + (rbase + 2 * p)     * 128 + lane * 4) = e;
            *(float4*)(g_pre1 + (rbase + 2 * p + 1) * 128 + lane * 4) = o;
        }

        if (it + 1 < TILES_PER_CTA) {
            __syncthreads();            // all warps done reading xT
            stage_x(tile + 1);
            __syncthreads();
        }
    }
}

// ---------------------------------------------------------------------------
// Branchless next-set-bit over a 128-bit mask (ascending k).
// ---------------------------------------------------------------------------
__device__ __forceinline__ int nextbit(ull& m0, ull& m1) {
    const bool lo = (m0 != 0ull);
    const ull  w  = lo ? m0 : m1;
    const ull  wc = w & (w - 1);
    const int  k  = (lo ? 0 : 64) + __ffsll((long long)w) - 1;
    m0 = lo ? wc : m0;
    m1 = lo ? m1 : wc;
    return k;
}

// Fixed-trip-count, depth-2 software-pipelined sparse accumulate.
// Ascending-k order (identical to all previous passing rounds).
__device__ __forceinline__ void walkp(
    const ulonglong2* __restrict__ W, ull m0, ull m1, int lane, ull& a, ull& b)
{
    int n = __popcll(m0) + __popcll(m1);
    if (n == 0) return;
    ulonglong2 va = W[nextbit(m0, m1) * 32 + lane];
    if (n >= 2) {
        ulonglong2 vb = W[nextbit(m0, m1) * 32 + lane];
        for (int i = 2; i < n; ++i) {
            ulonglong2 vc = W[nextbit(m0, m1) * 32 + lane];
            add2(a, va.x); add2(b, va.y);
            va = vb; vb = vc;
        }
        add2(a, va.x); add2(b, va.y);
        va = vb;
    }
    add2(a, va.x); add2(b, va.y);
}

// predicated lane-0 store (no BSSY/BSYNC)
__device__ __forceinline__ void stg_mask(ulonglong2* p, ull lo, ull hi, int lane) {
    asm volatile(
        "{\n\t.reg .pred p0;\n\tsetp.eq.s32 p0, %0, 0;\n\t"
        "@p0 st.global.v2.u64 [%1], {%2, %3};\n\t}"
        :: "r"(lane), "l"(p), "l"(lo), "l"(hi) : "memory");
}

// ---------------------------------------------------------------------------
// Kernel 2a: layer-1 recurrence, TWO rows per warp (interleaved chains).
// 64 CTAs x 128 thr.
// ---------------------------------------------------------------------------
__global__ void __launch_bounds__(128) k2a(void)
{
    extern __shared__ float sm[];      // 16384 f = permuted Wh1
    const int tid = threadIdx.x, lane = tid & 31, warp = tid >> 5;

    {
        const float4* Wp = (const float4*)g_Wh1p;
        float4* w4 = (float4*)sm;
        for (int i = tid; i < 4096; i += 128) w4[i] = Wp[i];
    }
    __syncthreads();

    const ulonglong2* W1 = (const ulonglong2*)sm;
    const int rA = (blockIdx.x * 4 + warp) * 2;
    const int rB = rA + 1;
    const float4* preA = (const float4*)g_pre1 + (size_t)rA * TS * 32 + lane;
    const float4* preB = (const float4*)g_pre1 + (size_t)rB * TS * 32 + lane;
    ulonglong2* msA = g_s1 + (size_t)rA * TS;
    ulonglong2* msB = g_s1 + (size_t)rB * TS;

    ull sA_lo = 0, sA_hi = 0, sB_lo = 0, sB_hi = 0;

    float4 fA0 = preA[0 * 32], fA1 = preA[1 * 32], fA2 = preA[2 * 32], fA3 = preA[3 * 32];
    float4 fB0 = preB[0 * 32], fB1 = preB[1 * 32], fB2 = preB[2 * 32], fB3 = preB[3 * 32];

    auto stepRow = [&](const float4& cur, ull& s_lo, ull& s_hi, ulonglong2* ms, int t) {
        ull h01 = pk2(cur.x, cur.y), h23 = pk2(cur.z, cur.w);
        walkp(W1, s_lo, s_hi, lane, h01, h23);
        const float2 ha = upk2(h01), hb = upk2(h23);
        const unsigned q0 = __ballot_sync(0xffffffffu, ha.x >= 1.0f);
        const unsigned q1 = __ballot_sync(0xffffffffu, ha.y >= 1.0f);
        const unsigned q2 = __ballot_sync(0xffffffffu, hb.x >= 1.0f);
        const unsigned q3 = __ballot_sync(0xffffffffu, hb.y >= 1.0f);
        s_lo = (ull)q0 | ((ull)q1 << 32);
        s_hi = (ull)q2 | ((ull)q3 << 32);
        stg_mask(ms + t, s_lo, s_hi, lane);
    };

    for (int t = 0; t < TS; t += 4) {
        stepRow(fA0, sA_lo, sA_hi, msA, t + 0); fA0 = preA[(t + 4) * 32];
        stepRow(fB0, sB_lo, sB_hi, msB, t + 0); fB0 = preB[(t + 4) * 32];
        stepRow(fA1, sA_lo, sA_hi, msA, t + 1); fA1 = preA[(t + 5) * 32];
        stepRow(fB1, sB_lo, sB_hi, msB, t + 1); fB1 = preB[(t + 5) * 32];
        stepRow(fA2, sA_lo, sA_hi, msA, t + 2); fA2 = preA[(t + 6) * 32];
        stepRow(fB2, sB_lo, sB_hi, msB, t + 2); fB2 = preB[(t + 6) * 32];
        stepRow(fA3, sA_lo, sA_hi, msA, t + 3); fA3 = preA[(t + 7) * 32];
        stepRow(fB3, sB_lo, sB_hi, msB, t + 3); fB3 = preB[(t + 7) * 32];
    }
}

// ---------------------------------------------------------------------------
// Kernel 2b1: gi(row,t) = b2 + s1(t)@Wi2^T. 512 CTAs x 256 thr = 4096 warps;
// warp w: row = w>>3, t-strip = (w&7)*125. Weights via L1-resident gmem.
// ---------------------------------------------------------------------------
__global__ void __launch_bounds__(256) k2b1(
    const float* __restrict__ bi2, const float* __restrict__ bh2)
{
    const int tid = threadIdx.x, lane = tid & 31;
    const int w    = blockIdx.x * 8 + (tid >> 5);
    const int row  = w >> 3;
    const int t0   = (w & 7) * (TS / 8);
    const int t1   = t0 + (TS / 8);

    const ulonglong2* W2i = (const ulonglong2*)(const void*)g_Wi2p;

    const ull b01 = pk2(bi2[lane]      + bh2[lane],      bi2[lane + 32] + bh2[lane + 32]);
    const ull b23 = pk2(bi2[lane + 64] + bh2[lane + 64], bi2[lane + 96] + bh2[lane + 96]);

    const ulonglong2* ms = g_s1 + (size_t)row * TS;
    ulonglong2* gi = (ulonglong2*)(void*)g_pre1 + (size_t)row * TS * 32 + lane;

    ulonglong2 mA = ms[t0], mB = ms[t0 + 1];
    for (int t = t0; t < t1; ++t) {
        const ulonglong2 m = mA;
        mA = mB;
        mB = ms[min(t + 2, t1 - 1)];
        ull g01 = b01, g23 = b23;
        walkp(W2i, m.x, m.y, lane, g01, g23);
        ulonglong2 o; o.x = g01; o.y = g23;
        gi[(size_t)t * 32] = o;
    }
}

// ---------------------------------------------------------------------------
// Kernel 2b2: layer-2 recurrence + counts + output, TWO rows per warp.
// 64 CTAs x 128 thr.
// ---------------------------------------------------------------------------
__global__ void __launch_bounds__(128) k2b2(
    const float* __restrict__ Wo, const float* __restrict__ bo,
    float* __restrict__ out)
{
    extern __shared__ float sm[];      // 16384 f = permuted Wh2
    const int tid = threadIdx.x, lane = tid & 31, warp = tid >> 5;

    {
        const float4* Wp = (const float4*)g_Wh2p;
        float4* w4 = (float4*)sm;
        for (int i = tid; i < 4096; i += 128) w4[i] = Wp[i];
    }
    __syncthreads();

    const ulonglong2* W2h = (const ulonglong2*)sm;
    const int rA = (blockIdx.x * 4 + warp) * 2;
    const int rB = rA + 1;
    const float4* giA = (const float4*)g_pre1 + (size_t)rA * TS * 32 + lane;
    const float4* giB = (const float4*)g_pre1 + (size_t)rB * TS * 32 + lane;

    ull rA_lo = 0, rA_hi = 0, rB_lo = 0, rB_hi = 0;
    int cA[4] = {0, 0, 0, 0}, cB[4] = {0, 0, 0, 0};

    float4 fA0 = giA[0 * 32], fA1 = giA[1 * 32], fA2 = giA[2 * 32], fA3 = giA[3 * 32];
    float4 fB0 = giB[0 * 32], fB1 = giB[1 * 32], fB2 = giB[2 * 32], fB3 = giB[3 * 32];

    auto stepRow = [&](const float4& cur, ull& r_lo, ull& r_hi, int* c) {
        ull g01 = pk2(cur.x, cur.y), g23 = pk2(cur.z, cur.w);
        walkp(W2h, r_lo, r_hi, lane, g01, g23);
        const float2 ga = upk2(g01), gb = upk2(g23);
        const bool p0 = (ga.x >= 1.0f), p1 = (ga.y >= 1.0f);
        const bool p2 = (gb.x >= 1.0f), p3 = (gb.y >= 1.0f);
        const unsigned q0 = __ballot_sync(0xffffffffu, p0);
        const unsigned q1 = __ballot_sync(0xffffffffu, p1);
        const unsigned q2 = __ballot_sync(0xffffffffu, p2);
        const unsigned q3 = __ballot_sync(0xffffffffu, p3);
        r_lo = (ull)q0 | ((ull)q1 << 32);
        r_hi = (ull)q2 | ((ull)q3 << 32);
        c[0] += p0; c[1] += p1; c[2] += p2; c[3] += p3;
    };

    for (int t = 0; t < TS; t += 4) {
        stepRow(fA0, rA_lo, rA_hi, cA); fA0 = giA[(t + 4) * 32];
        stepRow(fB0, rB_lo, rB_hi, cB); fB0 = giB[(t + 4) * 32];
        stepRow(fA1, rA_lo, rA_hi, cA); fA1 = giA[(t + 5) * 32];
        stepRow(fB1, rB_lo, rB_hi, cB); fB1 = giB[(t + 5) * 32];
        stepRow(fA2, rA_lo, rA_hi, cA); fA2 = giA[(t + 6) * 32];
        stepRow(fB2, rB_lo, rB_hi, cB); fB2 = giB[(t + 6) * 32];
        stepRow(fA3, rA_lo, rA_hi, cA); fA3 = giA[(t + 7) * 32];
        stepRow(fB3, rB_lo, rB_hi, cB); fB3 = giB[(t + 7) * 32];
    }

    auto epi = [&](const int* c, int row) {
        const float f0 = (float)c[0], f1 = (float)c[1], f2 = (float)c[2], f3 = (float)c[3];
#pragma unroll
        for (int o = 0; o < DOUT; ++o) {
            const float* wr = Wo + o * HD;
            float p = f0 * wr[lane] + f1 * wr[lane + 32]
                    + f2 * wr[lane + 64] + f3 * wr[lane + 96];
#pragma unroll
            for (int s = 16; s; s >>= 1) p += __shfl_xor_sync(0xffffffffu, p, s);
            if (lane == 0) out[row * DOUT + o] = bo[o] + p * (1.0f / (float)TS);
        }
    };
    epi(cA, rA);
    epi(cB, rB);
}

extern "C" void kernel_launch(void* const* d_in, const int* in_sizes, int n_in,
                              void* d_out, int out_size)
{
    const float* x   = (const float*)d_in[0];
    const float* Wi1 = (const float*)d_in[1];
    const float* bi1 = (const float*)d_in[2];
    const float* Wh1 = (const float*)d_in[3];
    const float* bh1 = (const float*)d_in[4];
    const float* Wi2 = (const float*)d_in[5];
    const float* bi2 = (const float*)d_in[6];
    const float* Wh2 = (const float*)d_in[7];
    const float* bh2 = (const float*)d_in[8];
    const float* Wo  = (const float*)d_in[9];
    const float* bo  = (const float*)d_in[10];
    float* out = (float*)d_out;

    const int k1_smem = (16384 + 128 * XS) * 4;   // 99328 B, 2 CTAs/SM
    const int w_smem  = 16384 * 4;                // 65536 B
    cudaFuncSetAttribute(k1_gemm, cudaFuncAttributeMaxDynamicSharedMemorySize, k1_smem);
    cudaFuncSetAttribute(k2a,  cudaFuncAttributeMaxDynamicSharedMemorySize, w_smem);
    cudaFuncSetAttribute(k2b2, cudaFuncAttributeMaxDynamicSharedMemorySize, w_smem);

    prep<<<64, 256>>>(Wi1, Wh1, Wi2, Wh2);
    k1_gemm<<<NTILES / TILES_PER_CTA, 256, k1_smem>>>(x, bi1, bh1);
    k2a<<<NB / 8, 128, w_smem>>>();
    k2b1<<<512, 256>>>(bi2, bh2);
    k2b2<<<NB / 8, 128, w_smem>>>(Wo, bo, out);
}

// round 14
// speedup vs baseline: 1.5374x; 1.4647x over previous
#include <cuda_runtime.h>
#include <cuda_bf16.h>
#include <cstdint>
#include <cstddef>

// SRNN_multi: 2-layer spiking RNN, N=512, T=1000, H=128, DOUT=20.
//   prep:  permute weight matrices once into gmem
//   k1:    pre1 = x @ Wi1^T + bi1 + bh1    (R10 GEMM, 1 tile/CTA)
//   k2a:   s1(t) recurrence -> mask stream (R10: 1 row/warp, 256 CTAs x 64)
//   k2b1:  gi(row,t) = b2 + s1(t)@Wi2^T    (R12: 4096-warp parallel, no smem)
//   k2b2:  s2(t) recurrence + counts       (R10: 1 row/warp, 256 CTAs x 64)
//   out = bo + (sum_t s2) @ Wo^T / T

#define NB   512
#define TS   1000
#define HD   128
#define DOUT 20
#define MTOT (NB * TS)
#define XS   66

typedef unsigned long long ull;

// pre1 scratch, permuted: [(row*TS+t)*128 + lane*4 + q] = val[lane + 32*q].
// Reused by k2b1 as gi storage. +2048 floats pad for deep prefetch overshoot.
__device__ float g_pre1[(size_t)MTOT * HD + 2048];
// s1 spike masks per (row,t): two 64-bit words (k 0-63, 64-127)
__device__ ulonglong2 g_s1[(size_t)NB * TS + 16];
// permuted weights: P[k*128 + (j&31)*4 + (j>>5)] = W[j*128 + k]
__device__ float g_Wi1p[HD * HD], g_Wh1p[HD * HD], g_Wi2p[HD * HD], g_Wh2p[HD * HD];

__device__ __forceinline__ ull pk2(float lo, float hi) {
    ull r; asm("mov.b64 %0, {%1, %2};" : "=l"(r) : "f"(lo), "f"(hi)); return r;
}
__device__ __forceinline__ float2 upk2(ull v) {
    float2 r; asm("mov.b64 {%0, %1}, %2;" : "=f"(r.x), "=f"(r.y) : "l"(v)); return r;
}
__device__ __forceinline__ void fma2(ull& d, ull a, ull b) {
    asm("fma.rn.f32x2 %0, %1, %2, %0;" : "+l"(d) : "l"(a), "l"(b));
}
__device__ __forceinline__ void add2(ull& d, ull a) {
    asm("add.rn.f32x2 %0, %1, %0;" : "+l"(d) : "l"(a));
}

// ---------------------------------------------------------------------------
// prep: one-time weight permutation.
// ---------------------------------------------------------------------------
__global__ void prep(const float* __restrict__ Wi1, const float* __restrict__ Wh1,
                     const float* __restrict__ Wi2, const float* __restrict__ Wh2)
{
    int i = blockIdx.x * blockDim.x + threadIdx.x;
    if (i < HD * HD) {
        int j = i >> 7, k = i & 127;
        int d = k * 128 + ((j & 31) << 2) + (j >> 5);
        g_Wi1p[d] = Wi1[i];
        g_Wh1p[d] = Wh1[i];
        g_Wi2p[d] = Wi2[i];
        g_Wh2p[d] = Wh2[i];
    }
}

// ---------------------------------------------------------------------------
// Kernel 1: pre1 = x @ Wi1^T + (bi1+bh1). R10 version, verbatim.
// 8000 CTAs x 256 thr; CTA = 64 rows; warp = 8 rows (4 row-pairs) x 128 cols.
// ---------------------------------------------------------------------------
__global__ void __launch_bounds__(256, 2) k1_gemm(
    const float* __restrict__ x, const float* __restrict__ bi1,
    const float* __restrict__ bh1)
{
    extern __shared__ float sm[];
    float* ws = sm;            // 16384 f: permuted Wi1
    float* xT = sm + 16384;    // 128*XS f: xT[k*XS + r]

    const int tid = threadIdx.x, lane = tid & 31, warp = tid >> 5;

    {
        const float4* Wp = (const float4*)g_Wi1p;
        float4* w4 = (float4*)ws;
        for (int i = tid; i < 4096; i += 256) w4[i] = Wp[i];
    }
    {
        const float4* xg = (const float4*)x + (size_t)blockIdx.x * 2048;
        for (int i = tid; i < 2048; i += 256) {
            float4 v = xg[i];
            int r = i >> 5, c = (i & 31) << 2;
            xT[(c + 0) * XS + r] = v.x;
            xT[(c + 1) * XS + r] = v.y;
            xT[(c + 2) * XS + r] = v.z;
            xT[(c + 3) * XS + r] = v.w;
        }
    }
    __syncthreads();

    ull acc[4][4];
#pragma unroll
    for (int q = 0; q < 4; ++q) {
        const float b = bi1[lane + 32 * q] + bh1[lane + 32 * q];
        const ull bd = pk2(b, b);
#pragma unroll
        for (int p = 0; p < 4; ++p) acc[q][p] = bd;
    }

    const float4* W4 = (const float4*)ws;
    const float* xw = xT + warp * 8;

#pragma unroll 4
    for (int k = 0; k < 128; ++k) {
        const float4 wv = W4[k * 32 + lane];
        const ull wd0 = pk2(wv.x, wv.x), wd1 = pk2(wv.y, wv.y);
        const ull wd2 = pk2(wv.z, wv.z), wd3 = pk2(wv.w, wv.w);
        const ull* xp = (const ull*)(xw + k * XS);
#pragma unroll
        for (int p = 0; p < 4; ++p) {
            const ull xv = xp[p];
            fma2(acc[0][p], xv, wd0);
            fma2(acc[1][p], xv, wd1);
            fma2(acc[2][p], xv, wd2);
            fma2(acc[3][p], xv, wd3);
        }
    }

    const size_t rbase = (size_t)blockIdx.x * 64 + warp * 8;
#pragma unroll
    for (int p = 0; p < 4; ++p) {
        const float2 a0 = upk2(acc[0][p]), a1 = upk2(acc[1][p]);
        const float2 a2 = upk2(acc[2][p]), a3 = upk2(acc[3][p]);
        float4 e; e.x = a0.x; e.y = a1.x; e.z = a2.x; e.w = a3.x;
        float4 o; o.x = a0.y; o.y = a1.y; o.z = a2.y; o.w = a3.y;
        *(float4*)(g_pre1 + (rbase + 2 * p)     * 128 + lane * 4) = e;
        *(float4*)(g_pre1 + (rbase + 2 * p + 1) * 128 + lane * 4) = o;
    }
}

// ---------------------------------------------------------------------------
// Branchless next-set-bit over a 128-bit mask (ascending k).
// ---------------------------------------------------------------------------
__device__ __forceinline__ int nextbit(ull& m0, ull& m1) {
    const bool lo = (m0 != 0ull);
    const ull  w  = lo ? m0 : m1;
    const ull  wc = w & (w - 1);
    const int  k  = (lo ? 0 : 64) + __ffsll((long long)w) - 1;
    m0 = lo ? wc : m0;
    m1 = lo ? m1 : wc;
    return k;
}

// Fixed-trip-count, depth-2 software-pipelined sparse accumulate.
// Ascending-k order (identical to all previous passing rounds).
__device__ __forceinline__ void walkp(
    const ulonglong2* __restrict__ W, ull m0, ull m1, int lane, ull& a, ull& b)
{
    int n = __popcll(m0) + __popcll(m1);
    if (n == 0) return;
    ulonglong2 va = W[nextbit(m0, m1) * 32 + lane];
    if (n >= 2) {
        ulonglong2 vb = W[nextbit(m0, m1) * 32 + lane];
        for (int i = 2; i < n; ++i) {
            ulonglong2 vc = W[nextbit(m0, m1) * 32 + lane];
            add2(a, va.x); add2(b, va.y);
            va = vb; vb = vc;
        }
        add2(a, va.x); add2(b, va.y);
        va = vb;
    }
    add2(a, va.x); add2(b, va.y);
}

// predicated lane-0 store (no BSSY/BSYNC)
__device__ __forceinline__ void stg_mask(ulonglong2* p, ull lo, ull hi, int lane) {
    asm volatile(
        "{\n\t.reg .pred p0;\n\tsetp.eq.s32 p0, %0, 0;\n\t"
        "@p0 st.global.v2.u64 [%1], {%2, %3};\n\t}"
        :: "r"(lane), "l"(p), "l"(lo), "l"(hi) : "memory");
}

// ---------------------------------------------------------------------------
// Kernel 2a: layer-1 recurrence. R10 version: 256 CTAs x 64 thr, 1 row/warp.
// Wh1 staged in smem; pre1 prefetched 8 deep.
// ---------------------------------------------------------------------------
__global__ void __launch_bounds__(64) k2a(void)
{
    extern __shared__ float sm[];      // 16384 f = permuted Wh1
    const int tid = threadIdx.x, lane = tid & 31, warp = tid >> 5;

    {
        const float4* Wp = (const float4*)g_Wh1p;
        float4* w4 = (float4*)sm;
        for (int i = tid; i < 4096; i += 64) w4[i] = Wp[i];
    }
    __syncthreads();

    const ulonglong2* W1 = (const ulonglong2*)sm;
    const int row = blockIdx.x * 2 + warp;
    const float4* pre = (const float4*)g_pre1 + (size_t)row * TS * 32 + lane;
    ulonglong2* ms = g_s1 + (size_t)row * TS;

    ull s_lo = 0, s_hi = 0;

    float4 f0 = pre[0 * 32], f1 = pre[1 * 32], f2 = pre[2 * 32], f3 = pre[3 * 32];
    float4 f4 = pre[4 * 32], f5 = pre[5 * 32], f6 = pre[6 * 32], f7 = pre[7 * 32];

    auto step = [&](const float4& cur, int t) {
        ull h01 = pk2(cur.x, cur.y), h23 = pk2(cur.z, cur.w);
        walkp(W1, s_lo, s_hi, lane, h01, h23);
        const float2 ha = upk2(h01), hb = upk2(h23);
        const unsigned q0 = __ballot_sync(0xffffffffu, ha.x >= 1.0f);
        const unsigned q1 = __ballot_sync(0xffffffffu, ha.y >= 1.0f);
        const unsigned q2 = __ballot_sync(0xffffffffu, hb.x >= 1.0f);
        const unsigned q3 = __ballot_sync(0xffffffffu, hb.y >= 1.0f);
        s_lo = (ull)q0 | ((ull)q1 << 32);
        s_hi = (ull)q2 | ((ull)q3 << 32);
        stg_mask(ms + t, s_lo, s_hi, lane);
    };

    for (int t = 0; t < TS; t += 8) {
        step(f0, t + 0); f0 = pre[(t +  8) * 32];
        step(f1, t + 1); f1 = pre[(t +  9) * 32];
        step(f2, t + 2); f2 = pre[(t + 10) * 32];
        step(f3, t + 3); f3 = pre[(t + 11) * 32];
        step(f4, t + 4); f4 = pre[(t + 12) * 32];
        step(f5, t + 5); f5 = pre[(t + 13) * 32];
        step(f6, t + 6); f6 = pre[(t + 14) * 32];
        step(f7, t + 7); f7 = pre[(t + 15) * 32];
    }
}

// ---------------------------------------------------------------------------
// Kernel 2b1: gi(row,t) = b2 + s1(t)@Wi2^T. R12 version (measured 188us):
// 512 CTAs x 256 thr = 4096 warps; warp w: row = w>>3, t-strip = (w&7)*125.
// Weights via L1-resident gmem (no smem -> no occupancy cap, no staging sync).
// ---------------------------------------------------------------------------
__global__ void __launch_bounds__(256) k2b1(
    const float* __restrict__ bi2, const float* __restrict__ bh2)
{
    const int tid = threadIdx.x, lane = tid & 31;
    const int w    = blockIdx.x * 8 + (tid >> 5);
    const int row  = w >> 3;
    const int t0   = (w & 7) * (TS / 8);
    const int t1   = t0 + (TS / 8);

    const ulonglong2* W2i = (const ulonglong2*)(const void*)g_Wi2p;

    const ull b01 = pk2(bi2[lane]      + bh2[lane],      bi2[lane + 32] + bh2[lane + 32]);
    const ull b23 = pk2(bi2[lane + 64] + bh2[lane + 64], bi2[lane + 96] + bh2[lane + 96]);

    const ulonglong2* ms = g_s1 + (size_t)row * TS;
    ulonglong2* gi = (ulonglong2*)(void*)g_pre1 + (size_t)row * TS * 32 + lane;

    ulonglong2 mA = ms[t0], mB = ms[t0 + 1];
    for (int t = t0; t < t1; ++t) {
        const ulonglong2 m = mA;
        mA = mB;
        mB = ms[min(t + 2, t1 - 1)];
        ull g01 = b01, g23 = b23;
        walkp(W2i, m.x, m.y, lane, g01, g23);
        ulonglong2 o; o.x = g01; o.y = g23;
        gi[(size_t)t * 32] = o;
    }
}

// ---------------------------------------------------------------------------
// Kernel 2b2: layer-2 recurrence + counts + output.
// R10 version: 256 CTAs x 64 thr, 1 row/warp, gi prefetched 8 deep.
// ---------------------------------------------------------------------------
__global__ void __launch_bounds__(64) k2b2(
    const float* __restrict__ Wo, const float* __restrict__ bo,
    float* __restrict__ out)
{
    extern __shared__ float sm[];      // 16384 f = permuted Wh2
    const int tid = threadIdx.x, lane = tid & 31, warp = tid >> 5;

    {
        const float4* Wp = (const float4*)g_Wh2p;
        float4* w4 = (float4*)sm;
        for (int i = tid; i < 4096; i += 64) w4[i] = Wp[i];
    }
    __syncthreads();

    const ulonglong2* W2h = (const ulonglong2*)sm;
    const int row = blockIdx.x * 2 + warp;
    const float4* gi = (const float4*)g_pre1 + (size_t)row * TS * 32 + lane;

    ull r2_lo = 0, r2_hi = 0;
    int c0 = 0, c1 = 0, c2 = 0, c3 = 0;

    float4 f0 = gi[0 * 32], f1 = gi[1 * 32], f2 = gi[2 * 32], f3 = gi[3 * 32];
    float4 f4 = gi[4 * 32], f5 = gi[5 * 32], f6 = gi[6 * 32], f7 = gi[7 * 32];

    auto stepB = [&](const float4& cur) {
        ull g01 = pk2(cur.x, cur.y), g23 = pk2(cur.z, cur.w);
        walkp(W2h, r2_lo, r2_hi, lane, g01, g23);
        const float2 ga = upk2(g01), gb = upk2(g23);
        const bool p0 = (ga.x >= 1.0f), p1 = (ga.y >= 1.0f);
        const bool p2 = (gb.x >= 1.0f), p3 = (gb.y >= 1.0f);
        const unsigned q0 = __ballot_sync(0xffffffffu, p0);
        const unsigned q1 = __ballot_sync(0xffffffffu, p1);
        const unsigned q2 = __ballot_sync(0xffffffffu, p2);
        const unsigned q3 = __ballot_sync(0xffffffffu, p3);
        r2_lo = (ull)q0 | ((ull)q1 << 32);
        r2_hi = (ull)q2 | ((ull)q3 << 32);
        c0 += p0; c1 += p1; c2 += p2; c3 += p3;
    };

    for (int t = 0; t < TS; t += 8) {
        stepB(f0); f0 = gi[(t +  8) * 32];
        stepB(f1); f1 = gi[(t +  9) * 32];
        stepB(f2); f2 = gi[(t + 10) * 32];
        stepB(f3); f3 = gi[(t + 11) * 32];
        stepB(f4); f4 = gi[(t + 12) * 32];
        stepB(f5); f5 = gi[(t + 13) * 32];
        stepB(f6); f6 = gi[(t + 14) * 32];
        stepB(f7); f7 = gi[(t + 15) * 32];
    }

    // out[row] = bo + counts @ Wo^T / T
    const float f0c = (float)c0, f1c = (float)c1, f2c = (float)c2, f3c = (float)c3;
#pragma unroll
    for (int o = 0; o < DOUT; ++o) {
        const float* wr = Wo + o * HD;
        float p = f0c * wr[lane] + f1c * wr[lane + 32]
                + f2c * wr[lane + 64] + f3c * wr[lane + 96];
#pragma unroll
        for (int s = 16; s; s >>= 1) p += __shfl_xor_sync(0xffffffffu, p, s);
        if (lane == 0) out[row * DOUT + o] = bo[o] + p * (1.0f / (float)TS);
    }
}

extern "C" void kernel_launch(void* const* d_in, const int* in_sizes, int n_in,
                              void* d_out, int out_size)
{
    const float* x   = (const float*)d_in[0];
    const float* Wi1 = (const float*)d_in[1];
    const float* bi1 = (const float*)d_in[2];
    const float* Wh1 = (const float*)d_in[3];
    const float* bh1 = (const float*)d_in[4];
    const float* Wi2 = (const float*)d_in[5];
    const float* bi2 = (const float*)d_in[6];
    const float* Wh2 = (const float*)d_in[7];
    const float* bh2 = (const float*)d_in[8];
    const float* Wo  = (const float*)d_in[9];
    const float* bo  = (const float*)d_in[10];
    float* out = (float*)d_out;

    const int k1_smem = (16384 + 128 * XS) * 4;   // 99328 B, 2 CTAs/SM
    const int w_smem  = 16384 * 4;                // 65536 B
    cudaFuncSetAttribute(k1_gemm, cudaFuncAttributeMaxDynamicSharedMemorySize, k1_smem);
    cudaFuncSetAttribute(k2a,  cudaFuncAttributeMaxDynamicSharedMemorySize, w_smem);
    cudaFuncSetAttribute(k2b2, cudaFuncAttributeMaxDynamicSharedMemorySize, w_smem);

    prep<<<64, 256>>>(Wi1, Wh1, Wi2, Wh2);
    k1_gemm<<<MTOT / 64, 256, k1_smem>>>(x, bi1, bh1);
    k2a<<<NB / 2, 64, w_smem>>>();
    k2b1<<<512, 256>>>(bi2, bh2);
    k2b2<<<NB / 2, 64, w_smem>>>(Wo, bo, out);
}